// round 5
// baseline (speedup 1.0000x reference)
#include <cuda_runtime.h>
#include <math.h>

#define TT 128
#define BB 32
#define EE 512
#define HH 512
#define UU 1024
#define VV 10000
#define G4 2048   // 4*H

#define NBLK 128          // persistent blocks, each owns 4 h-columns
#define SMEM_LSTM (8192 + 65536 + 65536)   // Pp + Wp + hs = 136KB

// ---------------- scratch (static device globals; no allocation) ----------------
__device__ __align__(128) float g_X1 [TT*G4*BB];   // transposed pregates [t][g4][b]
__device__ __align__(128) float g_H1 [TT*BB*HH];
__device__ __align__(128) float g_S  [TT*BB*UU];
__device__ __align__(128) float g_CTX[TT*BB*HH];
__device__ __align__(128) float g_X2 [TT*G4*BB];   // transposed pregates [t][g4][b]
__device__ __align__(128) float g_HS [TT*BB*HH];
__device__ __align__(128) float g_HT [2][HH*BB];   // parity h buffer [h][b]
__device__ unsigned g_flag[NBLK];

// ---------------- f32x2 helpers ----------------
__device__ __forceinline__ unsigned long long pack2(float x) {
    unsigned long long r;
    asm("mov.b64 %0, {%1, %1};" : "=l"(r) : "r"(__float_as_uint(x)));
    return r;
}
__device__ __forceinline__ void fma2(unsigned long long& d,
                                     unsigned long long a, unsigned long long b) {
    asm("fma.rn.f32x2 %0, %1, %2, %0;" : "+l"(d) : "l"(a), "l"(b));
}
__device__ __forceinline__ float sigmoidf_(float x) { return 1.f / (1.f + expf(-x)); }

// ---------------- prep: reset flags, transpose h0 slice into HT slot 1 ---------
__global__ void prep(const float* __restrict__ h0row)
{
    int i = threadIdx.x;
    if (i < NBLK) g_flag[i] = 0;
    for (int idx = i; idx < BB * HH; idx += 256) {
        int b = idx >> 9, h = idx & 511;
        g_HT[1][h * BB + b] = h0row[idx];
    }
}

// ---------------- persistent one-phase LSTM recurrence -------------------------
// Block bid owns h-cols [4*bid, 4*bid+4) => 16 gate rows, full K=512.
// W pre-packed duplicated f32x2 in smem (staged once). Per step: wait flags,
// stage h (coalesced copy from HT), 4-way k-split compute (f32x2), smem partial
// reduce + pointwise (c in registers), write h + HT, raise flag.
__global__ __launch_bounds__(256)
void lstm_seq(const float* __restrict__ XT,     // [T][G4][B] pregates
              const float* __restrict__ Whh,    // [G4][H]
              const float* __restrict__ c0row,  // [B][H]
              float* __restrict__ Hout)         // [T][B][H]
{
    extern __shared__ char smraw[];
    unsigned long long* Pp = (unsigned long long*)smraw;            // [4][256]
    unsigned long long* Wp = (unsigned long long*)(smraw + 8192);   // [512][16]
    float*              hs = (float*)(smraw + 8192 + 65536);        // [512][32]

    const int bid  = blockIdx.x;
    const int tid  = threadIdx.x;
    const int warp = tid >> 5;
    const int lane = tid & 31;

    // stage packed-dup W tile once: Wp[k*16 + rr], rr = g*4 + j
    for (int idx = tid; idx < 16 * 512; idx += 256) {
        int k = idx >> 4, rr = idx & 15;
        int grow = (rr >> 2) * 512 + bid * 4 + (rr & 3);
        Wp[idx] = pack2(Whh[(size_t)grow * HH + k]);
    }

    // compute-role constants
    const int s    = warp >> 1;          // k-slice 0..3  (k in [128s, 128s+128))
    const int half = warp & 1;           // pair half 0..1
    const int rg   = lane >> 2;          // row group 0..7  (rows 2rg, 2rg+1)
    const int pg   = lane & 3;           // pair group 0..3
    const int p0   = half * 8 + 2 * pg;  // pairs p0, p0+1
    const int kbeg = s * 128;

    // reducer-role constants + c in registers (tid < 128)
    const int rb  = tid & 31;
    const int rhl = (tid >> 5) & 3;
    const int hcol = bid * 4 + rhl;
    float cv = 0.f;
    if (tid < 128) cv = c0row[rb * HH + hcol];

    for (int t = 0; t < TT; t++) {
        // ---- wait for all blocks to finish step t-1 ----
        if (t > 0) {
            if (tid < NBLK) {
                volatile unsigned* f = &g_flag[tid];
                while (*f < (unsigned)t) { }
            }
            __threadfence();
        }
        __syncthreads();   // also covers Wp staging at t=0 and Pp/hs WAR

        // ---- stage h_{t-1}: straight coalesced copy HT[(t+1)&1] -> hs ----
        {
            const float4* src = (const float4*)g_HT[(t + 1) & 1];
            float4*       dst = (float4*)hs;
            #pragma unroll
            for (int r = 0; r < 16; r++) {
                int idx = tid + r * 256;
                dst[idx] = __ldcg(src + idx);
            }
        }
        __syncthreads();

        // ---- compute: 2 rows x 2 pairs per thread over 128 k (f32x2) ----
        unsigned long long a00 = 0ull, a01 = 0ull, a10 = 0ull, a11 = 0ull;
        #pragma unroll 8
        for (int k = kbeg; k < kbeg + 128; k++) {
            ulonglong2 wv = *(const ulonglong2*)&Wp[k * 16 + 2 * rg];
            ulonglong2 hv = *(const ulonglong2*)&hs[k * 32 + p0 * 2];
            fma2(a00, wv.x, hv.x);
            fma2(a01, wv.x, hv.y);
            fma2(a10, wv.y, hv.x);
            fma2(a11, wv.y, hv.y);
        }
        // store partials Pp[s][rr*16 + p]
        {
            unsigned long long* pb = Pp + s * 256;
            pb[(2 * rg)     * 16 + p0]     = a00;
            pb[(2 * rg)     * 16 + p0 + 1] = a01;
            pb[(2 * rg + 1) * 16 + p0]     = a10;
            pb[(2 * rg + 1) * 16 + p0 + 1] = a11;
        }
        __syncthreads();

        // ---- reduce + pointwise (tid < 128): cell (b=rb, h=hcol) ----
        if (tid < 128) {
            const float* pf = (const float*)Pp;
            const int pr = rb;   // float index within row block: pair*2+lohi == b
            float gate[4];
            #pragma unroll
            for (int g = 0; g < 4; g++) {
                int rr = g * 4 + rhl;
                int grow = g * 512 + hcol;
                float v = XT[((size_t)t * G4 + grow) * BB + rb];
                #pragma unroll
                for (int ss = 0; ss < 4; ss++)
                    v += pf[(ss * 256 + rr * 16) * 2 + pr];
                gate[g] = v;
            }
            float gi = sigmoidf_(gate[0]);
            float gf = sigmoidf_(gate[1]);
            float gg = tanhf(gate[2]);
            float go = sigmoidf_(gate[3]);
            cv = gf * cv + gi * gg;
            float hv = go * tanhf(cv);
            Hout[(size_t)t * BB * HH + rb * HH + hcol] = hv;
            g_HT[t & 1][hcol * BB + rb] = hv;
        }

        __threadfence();
        __syncthreads();
        if (tid == 0) *(volatile unsigned*)&g_flag[bid] = (unsigned)(t + 1);
    }
}

// ---------------- SGEMM  C = A(MxK) * B(NxK)^T + bias1 + bias2 ----------------
// transC=1: store C[(m>>5)][n][m&31] (i.e., [t][g4][b]) for the X pregate GEMMs.
__global__ __launch_bounds__(256)
void sgemm_tn(const float* __restrict__ A, const float* __restrict__ B,
              float* __restrict__ C,
              const float* __restrict__ bias1, const float* __restrict__ bias2,
              int M, int N, int K, int lda, int ldb, int ldc,
              long long aBS, long long bBS, long long cBS, int transC)
{
    __shared__ float As[16][64];
    __shared__ float Bs[16][64];

    const int tid = threadIdx.x;
    const int tx = tid & 15;
    const int ty = tid >> 4;
    const int m0 = blockIdx.y * 64;
    const int n0 = blockIdx.x * 64;

    const float* Ab = A + (long long)blockIdx.z * aBS;
    const float* Bb = B + (long long)blockIdx.z * bBS;
    float*       Cb = C + (long long)blockIdx.z * cBS;

    const int lr = tid >> 2;
    const int lk = (tid & 3) << 2;

    float acc[4][4];
    #pragma unroll
    for (int i = 0; i < 4; i++)
        #pragma unroll
        for (int j = 0; j < 4; j++) acc[i][j] = 0.f;

    for (int kt = 0; kt < K; kt += 16) {
        {
            int m = m0 + lr;
            float4 v = make_float4(0.f, 0.f, 0.f, 0.f);
            if (m < M) v = *(const float4*)(Ab + (size_t)m * lda + kt + lk);
            As[lk + 0][lr] = v.x; As[lk + 1][lr] = v.y;
            As[lk + 2][lr] = v.z; As[lk + 3][lr] = v.w;
        }
        {
            int n = n0 + lr;
            float4 v = make_float4(0.f, 0.f, 0.f, 0.f);
            if (n < N) v = *(const float4*)(Bb + (size_t)n * ldb + kt + lk);
            Bs[lk + 0][lr] = v.x; Bs[lk + 1][lr] = v.y;
            Bs[lk + 2][lr] = v.z; Bs[lk + 3][lr] = v.w;
        }
        __syncthreads();
        #pragma unroll
        for (int k = 0; k < 16; k++) {
            float a[4], b[4];
            *(float4*)a = *(const float4*)&As[k][ty << 2];
            *(float4*)b = *(const float4*)&Bs[k][tx << 2];
            #pragma unroll
            for (int i = 0; i < 4; i++)
                #pragma unroll
                for (int j = 0; j < 4; j++)
                    acc[i][j] += a[i] * b[j];
        }
        __syncthreads();
    }

    #pragma unroll
    for (int i = 0; i < 4; i++) {
        int m = m0 + (ty << 2) + i;
        if (m >= M) continue;
        #pragma unroll
        for (int j = 0; j < 4; j++) {
            int n = n0 + (tx << 2) + j;
            if (n < N) {
                float v = acc[i][j];
                if (bias1) v += bias1[n];
                if (bias2) v += bias2[n];
                if (transC)
                    Cb[((size_t)(m >> 5) * G4 + n) * BB + (m & 31)] = v;
                else
                    Cb[(size_t)m * ldc + n] = v;
            }
        }
    }
}

// ---------------- SGEMM  C = A(MxK) * B(KxN) ----------------
__global__ __launch_bounds__(256)
void sgemm_nn(const float* __restrict__ A, const float* __restrict__ B,
              float* __restrict__ C,
              int M, int N, int K, int lda, int ldb, int ldc,
              long long aBS, long long bBS, long long cBS)
{
    __shared__ float As[16][64];
    __shared__ float Bs[16][64];

    const int tid = threadIdx.x;
    const int tx = tid & 15;
    const int ty = tid >> 4;
    const int m0 = blockIdx.y * 64;
    const int n0 = blockIdx.x * 64;

    const float* Ab = A + (long long)blockIdx.z * aBS;
    const float* Bb = B + (long long)blockIdx.z * bBS;
    float*       Cb = C + (long long)blockIdx.z * cBS;

    const int lr = tid >> 2;
    const int lk = (tid & 3) << 2;
    const int bkr = tid >> 4;
    const int bnc = (tid & 15) << 2;

    float acc[4][4];
    #pragma unroll
    for (int i = 0; i < 4; i++)
        #pragma unroll
        for (int j = 0; j < 4; j++) acc[i][j] = 0.f;

    for (int kt = 0; kt < K; kt += 16) {
        {
            int m = m0 + lr;
            float4 v = make_float4(0.f, 0.f, 0.f, 0.f);
            if (m < M) v = *(const float4*)(Ab + (size_t)m * lda + kt + lk);
            As[lk + 0][lr] = v.x; As[lk + 1][lr] = v.y;
            As[lk + 2][lr] = v.z; As[lk + 3][lr] = v.w;
        }
        {
            int n = n0 + bnc;
            float4 v = make_float4(0.f, 0.f, 0.f, 0.f);
            if (n < N) v = *(const float4*)(Bb + (size_t)(kt + bkr) * ldb + n);
            *(float4*)&Bs[bkr][bnc] = v;
        }
        __syncthreads();
        #pragma unroll
        for (int k = 0; k < 16; k++) {
            float a[4], b[4];
            *(float4*)a = *(const float4*)&As[k][ty << 2];
            *(float4*)b = *(const float4*)&Bs[k][tx << 2];
            #pragma unroll
            for (int i = 0; i < 4; i++)
                #pragma unroll
                for (int j = 0; j < 4; j++)
                    acc[i][j] += a[i] * b[j];
        }
        __syncthreads();
    }

    #pragma unroll
    for (int i = 0; i < 4; i++) {
        int m = m0 + (ty << 2) + i;
        if (m >= M) continue;
        #pragma unroll
        for (int j = 0; j < 4; j++) {
            int n = n0 + (tx << 2) + j;
            if (n < N) Cb[(size_t)m * ldc + n] = acc[i][j];
        }
    }
}

// ---------------- row softmax (in place) ----------------
__global__ __launch_bounds__(256)
void softmax_rows(float* __restrict__ data, int L)
{
    float* p = data + (size_t)blockIdx.x * L;
    __shared__ float red[256];
    const int tid = threadIdx.x;

    float m = -3.4e38f;
    for (int i = tid; i < L; i += 256) m = fmaxf(m, p[i]);
    red[tid] = m; __syncthreads();
    #pragma unroll
    for (int s = 128; s > 0; s >>= 1) {
        if (tid < s) red[tid] = fmaxf(red[tid], red[tid + s]);
        __syncthreads();
    }
    m = red[0]; __syncthreads();

    float sum = 0.f;
    for (int i = tid; i < L; i += 256) {
        float e = expf(p[i] - m);
        p[i] = e;
        sum += e;
    }
    red[tid] = sum; __syncthreads();
    #pragma unroll
    for (int s = 128; s > 0; s >>= 1) {
        if (tid < s) red[tid] += red[tid + s];
        __syncthreads();
    }
    const float inv = 1.f / red[0];
    for (int i = tid; i < L; i += 256) p[i] *= inv;
}

// ---------------- launch ----------------
extern "C" void kernel_launch(void* const* d_in, const int* in_sizes, int n_in,
                              void* d_out, int out_size)
{
    const float* inputs = (const float*)d_in[0];
    const float* h0     = (const float*)d_in[1];
    const float* c0     = (const float*)d_in[2];
    const float* Lst    = (const float*)d_in[3];
    const float* W_ih1  = (const float*)d_in[4];
    const float* W_hh1  = (const float*)d_in[5];
    const float* b_ih1  = (const float*)d_in[6];
    const float* b_hh1  = (const float*)d_in[7];
    const float* W_ih2  = (const float*)d_in[8];
    const float* W_hh2  = (const float*)d_in[9];
    const float* b_ih2  = (const float*)d_in[10];
    const float* b_hh2  = (const float*)d_in[11];
    const float* W_out  = (const float*)d_in[12];
    const float* b_out  = (const float*)d_in[13];
    float* out = (float*)d_out;

    void* p;
    cudaGetSymbolAddress(&p, g_X1);  float* X1  = (float*)p;
    cudaGetSymbolAddress(&p, g_H1);  float* H1  = (float*)p;
    cudaGetSymbolAddress(&p, g_S);   float* S   = (float*)p;
    cudaGetSymbolAddress(&p, g_CTX); float* CTX = (float*)p;
    cudaGetSymbolAddress(&p, g_X2);  float* X2  = (float*)p;
    cudaGetSymbolAddress(&p, g_HS);  float* HS  = (float*)p;

    cudaFuncSetAttribute(lstm_seq, cudaFuncAttributeMaxDynamicSharedMemorySize,
                         SMEM_LSTM);

    // X1 = inputs @ W_ih1^T + biases, stored transposed [t][g4][b]
    {
        dim3 g(G4 / 64, (TT * BB) / 64, 1);
        sgemm_tn<<<g, 256>>>(inputs, W_ih1, X1, b_ih1, b_hh1,
                             TT * BB, G4, EE, EE, EE, G4, 0, 0, 0, 1);
    }

    // layer-1 recurrence
    prep<<<1, 256>>>(h0);
    lstm_seq<<<NBLK, 256, SMEM_LSTM>>>(X1, W_hh1, c0, H1);

    // attention: S[t,b,u] = sum_h H1[t,b,h] * L[u,b,h]
    {
        dim3 g(UU / 64, TT / 64, BB);
        sgemm_tn<<<g, 256>>>(H1, Lst, S, nullptr, nullptr,
                             TT, UU, HH, BB * HH, BB * HH, BB * UU,
                             HH, HH, UU, 0);
    }
    softmax_rows<<<TT * BB, 256>>>(S, UU);
    // CTX[t,b,h] = sum_u S[t,b,u] * L[u,b,h]
    {
        dim3 g(HH / 64, TT / 64, BB);
        sgemm_nn<<<g, 256>>>(S, Lst, CTX,
                             TT, HH, UU, BB * UU, BB * HH, BB * HH,
                             UU, HH, HH);
    }

    // X2 = CTX @ W_ih2^T + biases, stored transposed [t][g4][b]
    {
        dim3 g(G4 / 64, (TT * BB) / 64, 1);
        sgemm_tn<<<g, 256>>>(CTX, W_ih2, X2, b_ih2, b_hh2,
                             TT * BB, G4, HH, HH, HH, G4, 0, 0, 0, 1);
    }

    // layer-2 recurrence
    prep<<<1, 256>>>(h0 + BB * HH);
    lstm_seq<<<NBLK, 256, SMEM_LSTM>>>(X2, W_hh2, c0 + BB * HH, HS);

    // logits = HS @ W_out^T + b_out -> softmax over V
    {
        dim3 g((VV + 63) / 64, (TT * BB) / 64, 1);
        sgemm_tn<<<g, 256>>>(HS, W_out, out, b_out, nullptr,
                             TT * BB, VV, HH, HH, HH, VV, 0, 0, 0, 0);
    }
    softmax_rows<<<TT * BB, 256>>>(out, VV);
}

// round 6
// speedup vs baseline: 1.3499x; 1.3499x over previous
#include <cuda_runtime.h>
#include <math.h>

#define TT 128
#define BB 32
#define EE 512
#define HH 512
#define UU 1024
#define VV 10000
#define G4 2048   // 4*H

// recurrence decomposition: 32 h-col tiles (16 cols) x 4 batch groups (8 b)
#define NBLK 128
#define SMEM_LSTM (131072 + 32768 + 16384)   // Wt + hsd + Pp = 176KB

// ---------------- scratch (static device globals; no allocation) ----------------
__device__ __align__(128) float g_X1 [TT*G4*BB];   // pregates [t][g4][b]
__device__ __align__(128) float g_H1 [TT*BB*HH];
__device__ __align__(128) float g_S  [TT*BB*UU];
__device__ __align__(128) float g_CTX[TT*BB*HH];
__device__ __align__(128) float g_X2 [TT*G4*BB];   // pregates [t][g4][b]
__device__ __align__(128) float g_HS [TT*BB*HH];
__device__ __align__(128) float g_HT [2][4*512*8]; // parity h [bg][k][b8]
__device__ unsigned g_flag[NBLK];                  // [bg*32 + hc], monotonic

// ---------------- f32x2 / sync helpers ----------------
typedef unsigned long long ull;
__device__ __forceinline__ ull pack2(float x) {
    ull r;
    asm("mov.b64 %0, {%1, %1};" : "=l"(r) : "r"(__float_as_uint(x)));
    return r;
}
__device__ __forceinline__ void fma2(ull& d, ull a, ull b) {
    asm("fma.rn.f32x2 %0, %1, %2, %0;" : "+l"(d) : "l"(a), "l"(b));
}
__device__ __forceinline__ unsigned ld_acq(const unsigned* p) {
    unsigned v;
    asm volatile("ld.acquire.gpu.global.u32 %0, [%1];" : "=r"(v) : "l"(p));
    return v;
}
__device__ __forceinline__ void st_rel(unsigned* p, unsigned v) {
    asm volatile("st.release.gpu.global.u32 [%0], %1;" :: "l"(p), "r"(v) : "memory");
}
__device__ __forceinline__ float sigmoidf_(float x) { return 1.f / (1.f + expf(-x)); }

// ---------------- prep: reset flags, h0 -> g_HT[1] in [bg][k][b8] layout --------
__global__ void prep(const float* __restrict__ h0row)
{
    int tid = threadIdx.x;
    if (tid < NBLK) g_flag[tid] = 0;
    for (int idx = tid; idx < BB * HH; idx += 256) {
        int b = idx >> 9, h = idx & 511;
        g_HT[1][(b >> 3) * 4096 + h * 8 + (b & 7)] = h0row[idx];
    }
}

// ---------------- persistent LSTM recurrence -----------------------------------
// Block (hc, bg): h-cols [16hc,16hc+16), batches [8bg,8bg+8), full K=512.
// Complete gates locally (8-way k-split inside block, smem partials), pointwise
// locally, c in registers. One release-store flag per block per step; 32
// acquire-pollers. No fences, no cross-block reductions.
__global__ __launch_bounds__(256)
void lstm_seq(const float* __restrict__ XT,     // [T][G4][B] pregates
              const float* __restrict__ Whh,    // [G4][H]
              const float* __restrict__ c0row,  // [B][H]
              float* __restrict__ Hout)         // [T][B][H]
{
    extern __shared__ char smraw[];
    float* Wt  = (float*)smraw;                   // [512][64]  W transposed
    ull*   hsd = (ull*)(smraw + 131072);          // [512][8]   h duplicated
    ull*   Pp  = (ull*)(smraw + 131072 + 32768);  // [8][32][8] partials (row-pair lanes)

    const int bid = blockIdx.x;
    const int tid = threadIdx.x;
    const int hc  = bid & 31;
    const int bg  = bid >> 5;

    // ---- stage W tile once: Wt[k][r], r = g*16+j -> gate row g*512+16hc+j ----
    for (int idx = tid; idx < 64 * 128; idx += 256) {
        int r  = idx & 63;
        int k4 = idx >> 6;
        int g = r >> 4, j = r & 15;
        int gr = g * 512 + 16 * hc + j;
        float4 w = *(const float4*)(Whh + (size_t)gr * HH + k4 * 4);
        Wt[(k4 * 4 + 0) * 64 + r] = w.x;
        Wt[(k4 * 4 + 1) * 64 + r] = w.y;
        Wt[(k4 * 4 + 2) * 64 + r] = w.z;
        Wt[(k4 * 4 + 3) * 64 + r] = w.w;
    }

    const int warp = tid >> 5;
    const int lane = tid & 31;
    const int rg   = lane >> 1;        // 0..15 : rows 4rg..4rg+3 (2 row-pairs)
    const int bq   = lane & 1;         // 0..1  : batches 4bq..4bq+3
    const int kbeg = warp * 64;        // warp = k-slice

    // reducer/pointwise role (tid < 128): cell (j, bb)
    const int j  = tid >> 3;
    const int bb = tid & 7;
    float cv = 0.f;
    if (tid < 128) cv = c0row[(8 * bg + bb) * HH + 16 * hc + j];

    unsigned* myflag = &g_flag[bid];
    const unsigned* grpflags = &g_flag[bg * 32];

    for (int t = 0; t < TT; t++) {
        // ---- wait: all 32 same-bgrp blocks completed step t-1 ----
        if (t > 0) {
            if (tid < 32) {
                const unsigned* f = grpflags + tid;
                while (ld_acq(f) < (unsigned)t) { }
            }
        }
        __syncthreads();   // covers W staging (t=0), flag acquire, smem WAR

        // ---- stage h_{t-1} (own bgrp slice) -> hsd duplicated ----
        {
            const float4* src = (const float4*)&g_HT[(t + 1) & 1][bg * 4096];
            #pragma unroll
            for (int r = 0; r < 4; r++) {
                int i = tid + r * 256;            // 1024 float4 total
                float4 v = __ldcg(src + i);
                int k  = i >> 1;
                int b0 = (i & 1) * 4;
                ull* d = &hsd[k * 8 + b0];
                d[0] = pack2(v.x); d[1] = pack2(v.y);
                d[2] = pack2(v.z); d[3] = pack2(v.w);
            }
        }
        __syncthreads();

        // ---- compute: 2 row-pairs x 4 batches x 64 k (f32x2) ----
        ull acc[2][4];
        #pragma unroll
        for (int i = 0; i < 2; i++)
            #pragma unroll
            for (int q = 0; q < 4; q++) acc[i][q] = 0ull;

        #pragma unroll 4
        for (int k = kbeg; k < kbeg + 64; k++) {
            ulonglong2 wp = *(const ulonglong2*)&Wt[k * 64 + rg * 4];
            ulonglong2 hA = *(const ulonglong2*)&hsd[k * 8 + bq * 4];
            ulonglong2 hB = *(const ulonglong2*)&hsd[k * 8 + bq * 4 + 2];
            fma2(acc[0][0], wp.x, hA.x); fma2(acc[0][1], wp.x, hA.y);
            fma2(acc[0][2], wp.x, hB.x); fma2(acc[0][3], wp.x, hB.y);
            fma2(acc[1][0], wp.y, hA.x); fma2(acc[1][1], wp.y, hA.y);
            fma2(acc[1][2], wp.y, hB.x); fma2(acc[1][3], wp.y, hB.y);
        }

        // ---- store partials: Pp[slice][row-pair][b], lanes = 2 rows ----
        {
            ull* pb = &Pp[((warp * 32) + rg * 2) * 8 + bq * 4];
            *(ulonglong2*)(pb + 0)  = make_ulonglong2(acc[0][0], acc[0][1]);
            *(ulonglong2*)(pb + 2)  = make_ulonglong2(acc[0][2], acc[0][3]);
            *(ulonglong2*)(pb + 8)  = make_ulonglong2(acc[1][0], acc[1][1]);
            *(ulonglong2*)(pb + 10) = make_ulonglong2(acc[1][2], acc[1][3]);
        }
        __syncthreads();

        // ---- reduce + pointwise (tid < 128): cell (b = 8bg+bb, h = 16hc+j) ----
        if (tid < 128) {
            const float* pf = (const float*)Pp;
            float gate[4];
            #pragma unroll
            for (int g = 0; g < 4; g++) {
                int r  = g * 16 + j;
                int rp = r >> 1, ln = r & 1;
                float v = XT[((size_t)t * G4 + g * 512 + 16 * hc + j) * BB
                             + 8 * bg + bb];
                #pragma unroll
                for (int s = 0; s < 8; s++)
                    v += pf[((s * 32 + rp) * 8 + bb) * 2 + ln];
                gate[g] = v;
            }
            float gi = sigmoidf_(gate[0]);
            float gf = sigmoidf_(gate[1]);
            float gg = tanhf(gate[2]);
            float go = sigmoidf_(gate[3]);
            cv = gf * cv + gi * gg;
            float hv = go * tanhf(cv);
            Hout[(size_t)t * BB * HH + (8 * bg + bb) * HH + 16 * hc + j] = hv;
            g_HT[t & 1][bg * 4096 + (16 * hc + j) * 8 + bb] = hv;
        }

        __syncthreads();
        if (tid == 0) st_rel(myflag, (unsigned)(t + 1));
    }
}

// ---------------- SGEMM  C = A(MxK) * B(NxK)^T + bias1 + bias2 ----------------
// transC=1: store C[(m>>5)][n][m&31] ([t][g4][b]) for the X pregate GEMMs.
__global__ __launch_bounds__(256)
void sgemm_tn(const float* __restrict__ A, const float* __restrict__ B,
              float* __restrict__ C,
              const float* __restrict__ bias1, const float* __restrict__ bias2,
              int M, int N, int K, int lda, int ldb, int ldc,
              long long aBS, long long bBS, long long cBS, int transC)
{
    __shared__ float As[16][64];
    __shared__ float Bs[16][64];

    const int tid = threadIdx.x;
    const int tx = tid & 15;
    const int ty = tid >> 4;
    const int m0 = blockIdx.y * 64;
    const int n0 = blockIdx.x * 64;

    const float* Ab = A + (long long)blockIdx.z * aBS;
    const float* Bb = B + (long long)blockIdx.z * bBS;
    float*       Cb = C + (long long)blockIdx.z * cBS;

    const int lr = tid >> 2;
    const int lk = (tid & 3) << 2;

    float acc[4][4];
    #pragma unroll
    for (int i = 0; i < 4; i++)
        #pragma unroll
        for (int q = 0; q < 4; q++) acc[i][q] = 0.f;

    for (int kt = 0; kt < K; kt += 16) {
        {
            int m = m0 + lr;
            float4 v = make_float4(0.f, 0.f, 0.f, 0.f);
            if (m < M) v = *(const float4*)(Ab + (size_t)m * lda + kt + lk);
            As[lk + 0][lr] = v.x; As[lk + 1][lr] = v.y;
            As[lk + 2][lr] = v.z; As[lk + 3][lr] = v.w;
        }
        {
            int n = n0 + lr;
            float4 v = make_float4(0.f, 0.f, 0.f, 0.f);
            if (n < N) v = *(const float4*)(Bb + (size_t)n * ldb + kt + lk);
            Bs[lk + 0][lr] = v.x; Bs[lk + 1][lr] = v.y;
            Bs[lk + 2][lr] = v.z; Bs[lk + 3][lr] = v.w;
        }
        __syncthreads();
        #pragma unroll
        for (int k = 0; k < 16; k++) {
            float a[4], b[4];
            *(float4*)a = *(const float4*)&As[k][ty << 2];
            *(float4*)b = *(const float4*)&Bs[k][tx << 2];
            #pragma unroll
            for (int i = 0; i < 4; i++)
                #pragma unroll
                for (int q = 0; q < 4; q++)
                    acc[i][q] += a[i] * b[q];
        }
        __syncthreads();
    }

    #pragma unroll
    for (int i = 0; i < 4; i++) {
        int m = m0 + (ty << 2) + i;
        if (m >= M) continue;
        #pragma unroll
        for (int q = 0; q < 4; q++) {
            int n = n0 + (tx << 2) + q;
            if (n < N) {
                float v = acc[i][q];
                if (bias1) v += bias1[n];
                if (bias2) v += bias2[n];
                if (transC)
                    Cb[((size_t)(m >> 5) * G4 + n) * BB + (m & 31)] = v;
                else
                    Cb[(size_t)m * ldc + n] = v;
            }
        }
    }
}

// ---------------- SGEMM  C = A(MxK) * B(KxN) ----------------
__global__ __launch_bounds__(256)
void sgemm_nn(const float* __restrict__ A, const float* __restrict__ B,
              float* __restrict__ C,
              int M, int N, int K, int lda, int ldb, int ldc,
              long long aBS, long long bBS, long long cBS)
{
    __shared__ float As[16][64];
    __shared__ float Bs[16][64];

    const int tid = threadIdx.x;
    const int tx = tid & 15;
    const int ty = tid >> 4;
    const int m0 = blockIdx.y * 64;
    const int n0 = blockIdx.x * 64;

    const float* Ab = A + (long long)blockIdx.z * aBS;
    const float* Bb = B + (long long)blockIdx.z * bBS;
    float*       Cb = C + (long long)blockIdx.z * cBS;

    const int lr = tid >> 2;
    const int lk = (tid & 3) << 2;
    const int bkr = tid >> 4;
    const int bnc = (tid & 15) << 2;

    float acc[4][4];
    #pragma unroll
    for (int i = 0; i < 4; i++)
        #pragma unroll
        for (int q = 0; q < 4; q++) acc[i][q] = 0.f;

    for (int kt = 0; kt < K; kt += 16) {
        {
            int m = m0 + lr;
            float4 v = make_float4(0.f, 0.f, 0.f, 0.f);
            if (m < M) v = *(const float4*)(Ab + (size_t)m * lda + kt + lk);
            As[lk + 0][lr] = v.x; As[lk + 1][lr] = v.y;
            As[lk + 2][lr] = v.z; As[lk + 3][lr] = v.w;
        }
        {
            int n = n0 + bnc;
            float4 v = make_float4(0.f, 0.f, 0.f, 0.f);
            if (n < N) v = *(const float4*)(Bb + (size_t)(kt + bkr) * ldb + n);
            *(float4*)&Bs[bkr][bnc] = v;
        }
        __syncthreads();
        #pragma unroll
        for (int k = 0; k < 16; k++) {
            float a[4], b[4];
            *(float4*)a = *(const float4*)&As[k][ty << 2];
            *(float4*)b = *(const float4*)&Bs[k][tx << 2];
            #pragma unroll
            for (int i = 0; i < 4; i++)
                #pragma unroll
                for (int q = 0; q < 4; q++)
                    acc[i][q] += a[i] * b[q];
        }
        __syncthreads();
    }

    #pragma unroll
    for (int i = 0; i < 4; i++) {
        int m = m0 + (ty << 2) + i;
        if (m >= M) continue;
        #pragma unroll
        for (int q = 0; q < 4; q++) {
            int n = n0 + (tx << 2) + q;
            if (n < N) Cb[(size_t)m * ldc + n] = acc[i][q];
        }
    }
}

// ---------------- row softmax (in place) ----------------
__global__ __launch_bounds__(256)
void softmax_rows(float* __restrict__ data, int L)
{
    float* p = data + (size_t)blockIdx.x * L;
    __shared__ float red[256];
    const int tid = threadIdx.x;

    float m = -3.4e38f;
    for (int i = tid; i < L; i += 256) m = fmaxf(m, p[i]);
    red[tid] = m; __syncthreads();
    #pragma unroll
    for (int s = 128; s > 0; s >>= 1) {
        if (tid < s) red[tid] = fmaxf(red[tid], red[tid + s]);
        __syncthreads();
    }
    m = red[0]; __syncthreads();

    float sum = 0.f;
    for (int i = tid; i < L; i += 256) {
        float e = expf(p[i] - m);
        p[i] = e;
        sum += e;
    }
    red[tid] = sum; __syncthreads();
    #pragma unroll
    for (int s = 128; s > 0; s >>= 1) {
        if (tid < s) red[tid] += red[tid + s];
        __syncthreads();
    }
    const float inv = 1.f / red[0];
    for (int i = tid; i < L; i += 256) p[i] *= inv;
}

// ---------------- launch ----------------
extern "C" void kernel_launch(void* const* d_in, const int* in_sizes, int n_in,
                              void* d_out, int out_size)
{
    const float* inputs = (const float*)d_in[0];
    const float* h0     = (const float*)d_in[1];
    const float* c0     = (const float*)d_in[2];
    const float* Lst    = (const float*)d_in[3];
    const float* W_ih1  = (const float*)d_in[4];
    const float* W_hh1  = (const float*)d_in[5];
    const float* b_ih1  = (const float*)d_in[6];
    const float* b_hh1  = (const float*)d_in[7];
    const float* W_ih2  = (const float*)d_in[8];
    const float* W_hh2  = (const float*)d_in[9];
    const float* b_ih2  = (const float*)d_in[10];
    const float* b_hh2  = (const float*)d_in[11];
    const float* W_out  = (const float*)d_in[12];
    const float* b_out  = (const float*)d_in[13];
    float* out = (float*)d_out;

    void* p;
    cudaGetSymbolAddress(&p, g_X1);  float* X1  = (float*)p;
    cudaGetSymbolAddress(&p, g_H1);  float* H1  = (float*)p;
    cudaGetSymbolAddress(&p, g_S);   float* S   = (float*)p;
    cudaGetSymbolAddress(&p, g_CTX); float* CTX = (float*)p;
    cudaGetSymbolAddress(&p, g_X2);  float* X2  = (float*)p;
    cudaGetSymbolAddress(&p, g_HS);  float* HS  = (float*)p;

    cudaFuncSetAttribute(lstm_seq, cudaFuncAttributeMaxDynamicSharedMemorySize,
                         SMEM_LSTM);

    // X1 = inputs @ W_ih1^T + biases, stored [t][g4][b]
    {
        dim3 g(G4 / 64, (TT * BB) / 64, 1);
        sgemm_tn<<<g, 256>>>(inputs, W_ih1, X1, b_ih1, b_hh1,
                             TT * BB, G4, EE, EE, EE, G4, 0, 0, 0, 1);
    }

    // layer-1 recurrence
    prep<<<1, 256>>>(h0);
    lstm_seq<<<NBLK, 256, SMEM_LSTM>>>(X1, W_hh1, c0, H1);

    // attention: S[t,b,u] = sum_h H1[t,b,h] * L[u,b,h]
    {
        dim3 g(UU / 64, TT / 64, BB);
        sgemm_tn<<<g, 256>>>(H1, Lst, S, nullptr, nullptr,
                             TT, UU, HH, BB * HH, BB * HH, BB * UU,
                             HH, HH, UU, 0);
    }
    softmax_rows<<<TT * BB, 256>>>(S, UU);
    // CTX[t,b,h] = sum_u S[t,b,u] * L[u,b,h]
    {
        dim3 g(HH / 64, TT / 64, BB);
        sgemm_nn<<<g, 256>>>(S, Lst, CTX,
                             TT, HH, UU, BB * UU, BB * HH, BB * HH,
                             UU, HH, HH);
    }

    // X2 = CTX @ W_ih2^T + biases, stored [t][g4][b]
    {
        dim3 g(G4 / 64, (TT * BB) / 64, 1);
        sgemm_tn<<<g, 256>>>(CTX, W_ih2, X2, b_ih2, b_hh2,
                             TT * BB, G4, HH, HH, HH, G4, 0, 0, 0, 1);
    }

    // layer-2 recurrence
    prep<<<1, 256>>>(h0 + BB * HH);
    lstm_seq<<<NBLK, 256, SMEM_LSTM>>>(X2, W_hh2, c0 + BB * HH, HS);

    // logits = HS @ W_out^T + b_out -> softmax over V
    {
        dim3 g((VV + 63) / 64, (TT * BB) / 64, 1);
        sgemm_tn<<<g, 256>>>(HS, W_out, out, b_out, nullptr,
                             TT * BB, VV, HH, HH, HH, VV, 0, 0, 0, 0);
    }
    softmax_rows<<<TT * BB, 256>>>(out, VV);
}